// round 1
// baseline (speedup 1.0000x reference)
#include <cuda_runtime.h>
#include <math.h>

#define D_MODEL 1024
#define NHEAD   16
#define DH      64
#define BATCH   2
#define SEQ     2048
#define MROWS   (BATCH*SEQ)   // 4096
#define BHN     (BATCH*NHEAD) // 32

// Scratch (allocation-free): head-major [BHN, SEQ, DH] fp32 buffers.
__device__ float g_Q[BHN * SEQ * DH];
__device__ float g_K[BHN * SEQ * DH];
__device__ float g_V[BHN * SEQ * DH];
__device__ float g_O[BHN * SEQ * DH];

// ---------------------------------------------------------------------------
// Projection GEMM: out = (A[4096,1024] @ W[1024,1024] + b) * alpha
// scattered into head-major layout [BHN, SEQ, DH].
// BM=BN=64, BK=16, 256 threads, 4x4 register tile.
// ---------------------------------------------------------------------------
__global__ __launch_bounds__(256) void proj_gemm_kernel(
    const float* __restrict__ A, const float* __restrict__ W,
    const float* __restrict__ bias, int sel, float alpha)
{
    __shared__ __align__(16) float As[16 * 68];  // transposed: As[k][m]
    __shared__ __align__(16) float Ws[16 * 68];  // Ws[k][n]

    float* out = (sel == 0) ? g_Q : (sel == 1) ? g_K : g_V;

    const int bm = blockIdx.y * 64;
    const int bn = blockIdx.x * 64;
    const int tid = threadIdx.x;
    const int tx = tid & 15, ty = tid >> 4;

    // load indexing
    const int ar = tid >> 2;          // 0..63 (A row in tile)
    const int ac = (tid & 3) << 2;    // 0,4,8,12 (A k-chunk)
    const int wr = tid >> 4;          // 0..15 (W k row)
    const int wc = (tid & 15) << 2;   // 0..60 (W n col)

    float acc[4][4] = {};

    for (int kt = 0; kt < D_MODEL; kt += 16) {
        float4 a = *(const float4*)&A[(size_t)(bm + ar) * D_MODEL + kt + ac];
        As[(ac + 0) * 68 + ar] = a.x;
        As[(ac + 1) * 68 + ar] = a.y;
        As[(ac + 2) * 68 + ar] = a.z;
        As[(ac + 3) * 68 + ar] = a.w;
        float4 w = *(const float4*)&W[(size_t)(kt + wr) * D_MODEL + bn + wc];
        *(float4*)&Ws[wr * 68 + wc] = w;
        __syncthreads();

        #pragma unroll
        for (int kk = 0; kk < 16; kk++) {
            float4 av = *(const float4*)&As[kk * 68 + ty * 4];
            float4 wv = *(const float4*)&Ws[kk * 68 + tx * 4];
            float a4[4] = {av.x, av.y, av.z, av.w};
            float w4[4] = {wv.x, wv.y, wv.z, wv.w};
            #pragma unroll
            for (int i = 0; i < 4; i++)
                #pragma unroll
                for (int j = 0; j < 4; j++)
                    acc[i][j] += a4[i] * w4[j];
        }
        __syncthreads();
    }

    // Epilogue: bias + alpha, scatter to head-major [bb*NHEAD+h][t][d]
    const int bb = bm >> 11;      // row block is entirely inside one batch (2048 % 64 == 0)
    const int h  = bn >> 6;       // col block entirely inside one head
    float* ob = out + (size_t)(bb * NHEAD + h) * SEQ * DH;
    const float4 b4 = *(const float4*)&bias[bn + tx * 4];
    const float bb4[4] = {b4.x, b4.y, b4.z, b4.w};
    #pragma unroll
    for (int i = 0; i < 4; i++) {
        int t = (bm + ty * 4 + i) & (SEQ - 1);
        float4 o;
        o.x = (acc[i][0] + bb4[0]) * alpha;
        o.y = (acc[i][1] + bb4[1]) * alpha;
        o.z = (acc[i][2] + bb4[2]) * alpha;
        o.w = (acc[i][3] + bb4[3]) * alpha;
        *(float4*)&ob[(size_t)t * DH + tx * 4] = o;
    }
}

// ---------------------------------------------------------------------------
// Flash attention (fp32, online softmax). One CTA = 64 query rows of one
// (b,h). Streams K/V in 64-row tiles. Scale already folded into Q.
// Dynamic smem: Qs, Ks, Vs, Ss each [64][68] floats = 69632 bytes.
// ---------------------------------------------------------------------------
#define FLASH_SMEM (4 * 64 * 68 * 4)

__global__ __launch_bounds__(256) void flash_kernel()
{
    extern __shared__ __align__(16) float smem[];
    float* Qs = smem;
    float* Ks = Qs + 64 * 68;
    float* Vs = Ks + 64 * 68;
    float* Ss = Vs + 64 * 68;

    const int bh = blockIdx.y;
    const int q0 = blockIdx.x * 64;
    const float* Qp = g_Q + ((size_t)bh * SEQ + q0) * DH;
    const float* Kp = g_K + (size_t)bh * SEQ * DH;
    const float* Vp = g_V + (size_t)bh * SEQ * DH;

    const int tid = threadIdx.x;
    const int tx = tid & 15, ty = tid >> 4;

    // Load Q tile (64x64) once.
    #pragma unroll
    for (int i = tid; i < 1024; i += 256) {
        int r = i >> 4, c = (i & 15) << 2;
        *(float4*)&Qs[r * 68 + c] = *(const float4*)(Qp + r * DH + c);
    }

    float acc[4][4] = {};
    float mrow[4] = {-INFINITY, -INFINITY, -INFINITY, -INFINITY};
    float lrow[4] = {};

    for (int kt = 0; kt < SEQ; kt += 64) {
        __syncthreads();  // previous PV done reading Vs/Ss; Q load visible (iter 0)
        #pragma unroll
        for (int i = tid; i < 1024; i += 256) {
            int r = i >> 4, c = (i & 15) << 2;
            *(float4*)&Ks[r * 68 + c] = *(const float4*)(Kp + (kt + r) * DH + c);
            *(float4*)&Vs[r * 68 + c] = *(const float4*)(Vp + (kt + r) * DH + c);
        }
        __syncthreads();

        // S = Q @ K^T  (thread owns rows ty*4..+4, key cols tx*4..+4)
        float s[4][4] = {};
        #pragma unroll
        for (int d = 0; d < DH; d += 4) {
            float q[4][4], k[4][4];
            #pragma unroll
            for (int i = 0; i < 4; i++) {
                float4 t4 = *(const float4*)&Qs[(ty * 4 + i) * 68 + d];
                q[i][0] = t4.x; q[i][1] = t4.y; q[i][2] = t4.z; q[i][3] = t4.w;
            }
            #pragma unroll
            for (int j = 0; j < 4; j++) {
                float4 t4 = *(const float4*)&Ks[(tx * 4 + j) * 68 + d];
                k[j][0] = t4.x; k[j][1] = t4.y; k[j][2] = t4.z; k[j][3] = t4.w;
            }
            #pragma unroll
            for (int i = 0; i < 4; i++)
                #pragma unroll
                for (int j = 0; j < 4; j++)
                    #pragma unroll
                    for (int dd = 0; dd < 4; dd++)
                        s[i][j] += q[i][dd] * k[j][dd];
        }

        // Online softmax: row reduction across the 16 lanes sharing ty.
        #pragma unroll
        for (int i = 0; i < 4; i++) {
            float mx = fmaxf(fmaxf(s[i][0], s[i][1]), fmaxf(s[i][2], s[i][3]));
            #pragma unroll
            for (int off = 8; off > 0; off >>= 1)
                mx = fmaxf(mx, __shfl_xor_sync(0xffffffffu, mx, off, 16));
            float mnew = fmaxf(mrow[i], mx);
            float corr = __expf(mrow[i] - mnew);
            float ssum = 0.f;
            #pragma unroll
            for (int j = 0; j < 4; j++) {
                s[i][j] = __expf(s[i][j] - mnew);
                ssum += s[i][j];
            }
            #pragma unroll
            for (int off = 8; off > 0; off >>= 1)
                ssum += __shfl_xor_sync(0xffffffffu, ssum, off, 16);
            lrow[i] = lrow[i] * corr + ssum;
            mrow[i] = mnew;
            #pragma unroll
            for (int j = 0; j < 4; j++) acc[i][j] *= corr;
            *(float4*)&Ss[(ty * 4 + i) * 68 + tx * 4] =
                make_float4(s[i][0], s[i][1], s[i][2], s[i][3]);
        }
        __syncthreads();

        // acc += P @ V  (K-dim = 64 keys of this tile)
        #pragma unroll
        for (int kk = 0; kk < 64; kk += 4) {
            float p[4][4], v[4][4];
            #pragma unroll
            for (int i = 0; i < 4; i++) {
                float4 t4 = *(const float4*)&Ss[(ty * 4 + i) * 68 + kk];
                p[i][0] = t4.x; p[i][1] = t4.y; p[i][2] = t4.z; p[i][3] = t4.w;
            }
            #pragma unroll
            for (int r = 0; r < 4; r++) {
                float4 t4 = *(const float4*)&Vs[(kk + r) * 68 + tx * 4];
                v[r][0] = t4.x; v[r][1] = t4.y; v[r][2] = t4.z; v[r][3] = t4.w;
            }
            #pragma unroll
            for (int i = 0; i < 4; i++)
                #pragma unroll
                for (int j = 0; j < 4; j++)
                    #pragma unroll
                    for (int r = 0; r < 4; r++)
                        acc[i][j] += p[i][r] * v[r][j];
        }
    }

    // Epilogue: divide by l, write head-major O.
    float* Op = g_O + ((size_t)bh * SEQ + q0) * DH;
    #pragma unroll
    for (int i = 0; i < 4; i++) {
        float inv = 1.0f / lrow[i];
        float4 o;
        o.x = acc[i][0] * inv;
        o.y = acc[i][1] * inv;
        o.z = acc[i][2] * inv;
        o.w = acc[i][3] * inv;
        *(float4*)&Op[(size_t)(ty * 4 + i) * DH + tx * 4] = o;
    }
}

// ---------------------------------------------------------------------------
// Output GEMM: C = concat(O) @ Wo + bo, A gathered from head-major g_O.
// ---------------------------------------------------------------------------
__global__ __launch_bounds__(256) void out_gemm_kernel(
    const float* __restrict__ W, const float* __restrict__ bias,
    float* __restrict__ Cout)
{
    __shared__ __align__(16) float As[16 * 68];
    __shared__ __align__(16) float Ws[16 * 68];

    const int bm = blockIdx.y * 64;
    const int bn = blockIdx.x * 64;
    const int tid = threadIdx.x;
    const int tx = tid & 15, ty = tid >> 4;

    const int ar = tid >> 2;
    const int ac = (tid & 3) << 2;
    const int wr = tid >> 4;
    const int wc = (tid & 15) << 2;

    const int bb = bm >> 11;
    const int t  = (bm + ar) & (SEQ - 1);

    float acc[4][4] = {};

    for (int kt = 0; kt < D_MODEL; kt += 16) {
        // A[m][k] = g_O[((bb*NHEAD + k/64)*SEQ + t)*DH + k%64]; 16-chunk stays in one head
        const int h  = kt >> 6;
        const int d0 = kt & 63;
        float4 a = *(const float4*)&g_O[((size_t)(bb * NHEAD + h) * SEQ + t) * DH + d0 + ac];
        As[(ac + 0) * 68 + ar] = a.x;
        As[(ac + 1) * 68 + ar] = a.y;
        As[(ac + 2) * 68 + ar] = a.z;
        As[(ac + 3) * 68 + ar] = a.w;
        float4 w = *(const float4*)&W[(size_t)(kt + wr) * D_MODEL + bn + wc];
        *(float4*)&Ws[wr * 68 + wc] = w;
        __syncthreads();

        #pragma unroll
        for (int kk = 0; kk < 16; kk++) {
            float4 av = *(const float4*)&As[kk * 68 + ty * 4];
            float4 wv = *(const float4*)&Ws[kk * 68 + tx * 4];
            float a4[4] = {av.x, av.y, av.z, av.w};
            float w4[4] = {wv.x, wv.y, wv.z, wv.w};
            #pragma unroll
            for (int i = 0; i < 4; i++)
                #pragma unroll
                for (int j = 0; j < 4; j++)
                    acc[i][j] += a4[i] * w4[j];
        }
        __syncthreads();
    }

    const float4 b4 = *(const float4*)&bias[bn + tx * 4];
    const float bb4[4] = {b4.x, b4.y, b4.z, b4.w};
    #pragma unroll
    for (int i = 0; i < 4; i++) {
        float4 o;
        o.x = acc[i][0] + bb4[0];
        o.y = acc[i][1] + bb4[1];
        o.z = acc[i][2] + bb4[2];
        o.w = acc[i][3] + bb4[3];
        *(float4*)&Cout[(size_t)(bm + ty * 4 + i) * D_MODEL + bn + tx * 4] = o;
    }
}

// ---------------------------------------------------------------------------
extern "C" void kernel_launch(void* const* d_in, const int* in_sizes, int n_in,
                              void* d_out, int out_size)
{
    const float* x  = (const float*)d_in[0];
    const float* Wq = (const float*)d_in[1];
    const float* bq = (const float*)d_in[2];
    const float* Wk = (const float*)d_in[3];
    const float* bk = (const float*)d_in[4];
    const float* Wv = (const float*)d_in[5];
    const float* bv = (const float*)d_in[6];
    const float* Wo = (const float*)d_in[7];
    const float* bo = (const float*)d_in[8];

    (void)in_sizes; (void)n_in; (void)out_size;

    dim3 gg(D_MODEL / 64, MROWS / 64);  // (16, 64)
    dim3 bb(256);

    const float scale = 0.125f;  // 1/sqrt(DH), folded into Q (incl. bias)
    proj_gemm_kernel<<<gg, bb>>>(x, Wq, bq, 0, scale);
    proj_gemm_kernel<<<gg, bb>>>(x, Wk, bk, 1, 1.0f);
    proj_gemm_kernel<<<gg, bb>>>(x, Wv, bv, 2, 1.0f);

    cudaFuncSetAttribute(flash_kernel,
                         cudaFuncAttributeMaxDynamicSharedMemorySize, FLASH_SMEM);
    flash_kernel<<<dim3(SEQ / 64, BHN), 256, FLASH_SMEM>>>();

    out_gemm_kernel<<<gg, bb>>>(Wo, bo, (float*)d_out);
}

// round 3
// speedup vs baseline: 3.6725x; 3.6725x over previous
#include <cuda_runtime.h>
#include <math.h>
#include <stdint.h>

#define D_MODEL 1024
#define NHEAD   16
#define DH      64
#define BATCH   2
#define SEQ     2048
#define MROWS   (BATCH*SEQ)   // 4096
#define BHN     (BATCH*NHEAD) // 32

// Scratch (allocation-free): head-major [BHN, SEQ, DH] fp32 buffers.
__device__ float g_Q[BHN * SEQ * DH];
__device__ float g_K[BHN * SEQ * DH];
__device__ float g_V[BHN * SEQ * DH];
__device__ float g_O[BHN * SEQ * DH];

// ---------------------------------------------------------------------------
// helpers
// ---------------------------------------------------------------------------
__device__ __forceinline__ uint32_t f2tf(float f) {
    uint32_t u;
    asm("cvt.rna.tf32.f32 %0, %1;" : "=r"(u) : "f"(f));
    return u;
}

// D += A(16x8,row) * B(8x8,col) ; tf32 in, fp32 accumulate
__device__ __forceinline__ void mma8(float* c, const uint32_t* a,
                                     uint32_t b0, uint32_t b1) {
    asm volatile(
        "mma.sync.aligned.m16n8k8.row.col.f32.tf32.tf32.f32 "
        "{%0,%1,%2,%3}, {%4,%5,%6,%7}, {%8,%9}, {%0,%1,%2,%3};"
        : "+f"(c[0]), "+f"(c[1]), "+f"(c[2]), "+f"(c[3])
        : "r"(a[0]), "r"(a[1]), "r"(a[2]), "r"(a[3]), "r"(b0), "r"(b1));
}

// ---------------------------------------------------------------------------
// tf32 tensor GEMM: C[4096,1024] = A[4096,1024] @ W[1024,1024] (+bias)*alpha
// mode 0/1/2: A = x, epilogue scatters head-major into g_Q/g_K/g_V
// mode 3:     A gathered from g_O head-major, epilogue -> Cout
// CTA 128x128, BK=32, double-buffered. 8 warps (2x4), warp tile 64x32.
// ---------------------------------------------------------------------------
#define BK      32
#define NS      (D_MODEL / BK)    // 32
#define AS_STR  36
#define WS_STR  136
#define BUFSZ   (128*AS_STR + BK*WS_STR)   // 8960 words
#define GEMM_SMEM (2 * BUFSZ * 4)          // 71680 B

__global__ __launch_bounds__(256) void tc_gemm_kernel(
    const float* __restrict__ A, const float* __restrict__ W,
    const float* __restrict__ bias, float* __restrict__ Cout,
    int mode, float alpha)
{
    extern __shared__ __align__(16) uint32_t sm[];

    const int tid  = threadIdx.x;
    const int w    = tid >> 5, lane = tid & 31;
    const int wm   = w >> 2, wn = w & 3;
    const int m0w  = wm * 64, n0w = wn * 32;
    const int bm   = blockIdx.y * 128, bn = blockIdx.x * 128;
    const int bb   = bm >> 11;

    float4 pa[4], pw[4];

    auto ldgA = [&](int kt, float4* p) {
        #pragma unroll
        for (int i = 0; i < 4; i++) {
            int idx = tid + 256 * i;
            int row = idx >> 3, c4 = (idx & 7) * 4;
            const float* src;
            if (mode < 3) {
                src = A + (size_t)(bm + row) * D_MODEL + kt + c4;
            } else {
                int h = kt >> 6;
                int t = (bm + row) & (SEQ - 1);
                src = g_O + (((size_t)(bb * NHEAD + h)) * SEQ + t) * DH
                      + (kt & 63) + c4;
            }
            p[i] = *(const float4*)src;
        }
    };
    auto ldgW = [&](int kt, float4* p) {
        #pragma unroll
        for (int i = 0; i < 4; i++) {
            int idx = tid + 256 * i;
            int k = idx >> 5, n4 = (idx & 31) * 4;
            p[i] = *(const float4*)(W + (size_t)(kt + k) * D_MODEL + bn + n4);
        }
    };
    auto stsA = [&](uint32_t* dst, const float4* p) {
        #pragma unroll
        for (int i = 0; i < 4; i++) {
            int idx = tid + 256 * i;
            int row = idx >> 3, c4 = (idx & 7) * 4;
            uint4 u = make_uint4(f2tf(p[i].x), f2tf(p[i].y),
                                 f2tf(p[i].z), f2tf(p[i].w));
            *(uint4*)&dst[row * AS_STR + c4] = u;
        }
    };
    auto stsW = [&](uint32_t* dst, const float4* p) {
        #pragma unroll
        for (int i = 0; i < 4; i++) {
            int idx = tid + 256 * i;
            int k = idx >> 5, n4 = (idx & 31) * 4;
            uint4 u = make_uint4(f2tf(p[i].x), f2tf(p[i].y),
                                 f2tf(p[i].z), f2tf(p[i].w));
            *(uint4*)&dst[k * WS_STR + n4] = u;
        }
    };

    ldgA(0, pa); ldgW(0, pw);
    stsA(sm, pa); stsW(sm + 128 * AS_STR, pw);
    __syncthreads();

    float acc[4][4][4] = {};

    #pragma unroll 1
    for (int s = 0; s < NS; s++) {
        const int buf = s & 1;
        if (s + 1 < NS) { ldgA((s + 1) * BK, pa); ldgW((s + 1) * BK, pw); }

        uint32_t* As_ = sm + buf * BUFSZ;
        uint32_t* Ws_ = As_ + 128 * AS_STR;

        #pragma unroll
        for (int k8 = 0; k8 < 4; k8++) {
            const int k0 = k8 * 8;
            uint32_t a[4][4];
            #pragma unroll
            for (int mt = 0; mt < 4; mt++) {
                int r = m0w + mt * 16 + (lane >> 2);
                int c = k0 + (lane & 3);
                a[mt][0] = As_[r * AS_STR + c];
                a[mt][1] = As_[(r + 8) * AS_STR + c];
                a[mt][2] = As_[r * AS_STR + c + 4];
                a[mt][3] = As_[(r + 8) * AS_STR + c + 4];
            }
            #pragma unroll
            for (int nt = 0; nt < 4; nt++) {
                int n = n0w + nt * 8 + (lane >> 2);
                uint32_t b0 = Ws_[(k0 + (lane & 3)) * WS_STR + n];
                uint32_t b1 = Ws_[(k0 + (lane & 3) + 4) * WS_STR + n];
                #pragma unroll
                for (int mt = 0; mt < 4; mt++)
                    mma8(acc[mt][nt], a[mt], b0, b1);
            }
        }
        __syncthreads();
        if (s + 1 < NS) {
            uint32_t* Ad = sm + (buf ^ 1) * BUFSZ;
            stsA(Ad, pa); stsW(Ad + 128 * AS_STR, pw);
            __syncthreads();
        }
    }

    // Epilogue: c0/c1 -> (row, 2c..2c+1), c2/c3 -> (row+8, ...)
    float* outp = (mode == 0) ? g_Q : (mode == 1) ? g_K : g_V;
    #pragma unroll
    for (int mt = 0; mt < 4; mt++) {
        #pragma unroll
        for (int nt = 0; nt < 4; nt++) {
            int rl = m0w + mt * 16 + (lane >> 2);
            int cl = n0w + nt * 8 + (lane & 3) * 2;
            float2 bv = *(const float2*)&bias[bn + cl];
            float2 o0, o1;
            o0.x = (acc[mt][nt][0] + bv.x) * alpha;
            o0.y = (acc[mt][nt][1] + bv.y) * alpha;
            o1.x = (acc[mt][nt][2] + bv.x) * alpha;
            o1.y = (acc[mt][nt][3] + bv.y) * alpha;
            if (mode == 3) {
                *(float2*)&Cout[(size_t)(bm + rl) * D_MODEL + bn + cl] = o0;
                *(float2*)&Cout[(size_t)(bm + rl + 8) * D_MODEL + bn + cl] = o1;
            } else {
                int col = bn + cl;
                int h = col >> 6, d = col & 63;
                int t0 = (bm + rl) & (SEQ - 1);
                float* ob = outp + ((size_t)(bb * NHEAD + h)) * SEQ * DH;
                *(float2*)&ob[(size_t)t0 * DH + d] = o0;
                *(float2*)&ob[(size_t)(t0 + 8) * DH + d] = o1;
            }
        }
    }
}

// ---------------------------------------------------------------------------
// Flash attention with tf32 MMA. CTA = 128 queries, 8 warps x 16-row slabs,
// KV tiles of 64. QK^T and PV on tensor pipe; softmax fp32, shfl-only.
// ---------------------------------------------------------------------------
#define QS_STR 68
#define KS_STR 68
#define VS_STR 72
#define SS_STR 68
#define FLASH_SMEM ((128*QS_STR + 64*KS_STR + 64*VS_STR + 128*SS_STR) * 4)

__global__ __launch_bounds__(256) void flash_kernel()
{
    extern __shared__ __align__(16) uint32_t fs[];
    uint32_t* Qs = fs;
    uint32_t* Ks = Qs + 128 * QS_STR;
    uint32_t* Vs = Ks + 64 * KS_STR;
    uint32_t* Ss = Vs + 64 * VS_STR;

    const int tid = threadIdx.x;
    const int w = tid >> 5, lane = tid & 31;
    const int bh = blockIdx.y;
    const int q0 = blockIdx.x * 128;

    const float* Qp = g_Q + ((size_t)bh * SEQ + q0) * DH;
    const float* Kp = g_K + (size_t)bh * SEQ * DH;
    const float* Vp = g_V + (size_t)bh * SEQ * DH;

    // Q load: warp-local 16-row slab, tf32-converted.
    #pragma unroll
    for (int i = 0; i < 8; i++) {
        int idx = lane + 32 * i;
        int row = w * 16 + (idx >> 4), c4 = (idx & 15) * 4;
        float4 v = *(const float4*)(Qp + (size_t)row * DH + c4);
        *(uint4*)&Qs[row * QS_STR + c4] =
            make_uint4(f2tf(v.x), f2tf(v.y), f2tf(v.z), f2tf(v.w));
    }

    const int r0 = lane >> 2;
    const int qrow = w * 16 + r0;

    float o[8][4] = {};
    float m0 = -INFINITY, m1 = -INFINITY, l0 = 0.f, l1 = 0.f;

    #pragma unroll 1
    for (int kt = 0; kt < SEQ; kt += 64) {
        __syncthreads();
        #pragma unroll
        for (int i = 0; i < 4; i++) {
            int idx = tid + 256 * i;
            int row = idx >> 4, c4 = (idx & 15) * 4;
            float4 kv = *(const float4*)(Kp + (size_t)(kt + row) * DH + c4);
            *(uint4*)&Ks[row * KS_STR + c4] =
                make_uint4(f2tf(kv.x), f2tf(kv.y), f2tf(kv.z), f2tf(kv.w));
            float4 vv = *(const float4*)(Vp + (size_t)(kt + row) * DH + c4);
            *(uint4*)&Vs[row * VS_STR + c4] =
                make_uint4(f2tf(vv.x), f2tf(vv.y), f2tf(vv.z), f2tf(vv.w));
        }
        __syncthreads();

        // S = Q @ K^T : 8 n-tiles (64 keys), 8 k-steps (DH=64)
        float s[8][4] = {};
        #pragma unroll
        for (int k8 = 0; k8 < 8; k8++) {
            const int k0 = k8 * 8;
            uint32_t a[4];
            a[0] = Qs[qrow * QS_STR + k0 + (lane & 3)];
            a[1] = Qs[(qrow + 8) * QS_STR + k0 + (lane & 3)];
            a[2] = Qs[qrow * QS_STR + k0 + (lane & 3) + 4];
            a[3] = Qs[(qrow + 8) * QS_STR + k0 + (lane & 3) + 4];
            #pragma unroll
            for (int nt = 0; nt < 8; nt++) {
                int key = nt * 8 + (lane >> 2);
                uint32_t b0 = Ks[key * KS_STR + k0 + (lane & 3)];
                uint32_t b1 = Ks[key * KS_STR + k0 + (lane & 3) + 4];
                mma8(s[nt], a, b0, b1);
            }
        }

        // online softmax (rows r0 -> regs 0/1, r0+8 -> regs 2/3)
        float mx0 = -INFINITY, mx1 = -INFINITY;
        #pragma unroll
        for (int nt = 0; nt < 8; nt++) {
            mx0 = fmaxf(mx0, fmaxf(s[nt][0], s[nt][1]));
            mx1 = fmaxf(mx1, fmaxf(s[nt][2], s[nt][3]));
        }
        mx0 = fmaxf(mx0, __shfl_xor_sync(0xffffffffu, mx0, 1));
        mx0 = fmaxf(mx0, __shfl_xor_sync(0xffffffffu, mx0, 2));
        mx1 = fmaxf(mx1, __shfl_xor_sync(0xffffffffu, mx1, 1));
        mx1 = fmaxf(mx1, __shfl_xor_sync(0xffffffffu, mx1, 2));

        float mn0 = fmaxf(m0, mx0), mn1 = fmaxf(m1, mx1);
        float c0 = __expf(m0 - mn0), c1 = __expf(m1 - mn1);
        m0 = mn0; m1 = mn1;

        float sum0 = 0.f, sum1 = 0.f;
        #pragma unroll
        for (int nt = 0; nt < 8; nt++) {
            s[nt][0] = __expf(s[nt][0] - mn0); sum0 += s[nt][0];
            s[nt][1] = __expf(s[nt][1] - mn0); sum0 += s[nt][1];
            s[nt][2] = __expf(s[nt][2] - mn1); sum1 += s[nt][2];
            s[nt][3] = __expf(s[nt][3] - mn1); sum1 += s[nt][3];
        }
        sum0 += __shfl_xor_sync(0xffffffffu, sum0, 1);
        sum0 += __shfl_xor_sync(0xffffffffu, sum0, 2);
        sum1 += __shfl_xor_sync(0xffffffffu, sum1, 1);
        sum1 += __shfl_xor_sync(0xffffffffu, sum1, 2);
        l0 = l0 * c0 + sum0;
        l1 = l1 * c1 + sum1;

        #pragma unroll
        for (int nt = 0; nt < 8; nt++) {
            o[nt][0] *= c0; o[nt][1] *= c0;
            o[nt][2] *= c1; o[nt][3] *= c1;
        }

        __syncwarp();
        #pragma unroll
        for (int nt = 0; nt < 8; nt++) {
            int col = nt * 8 + (lane & 3) * 2;
            *(uint2*)&Ss[qrow * SS_STR + col] =
                make_uint2(f2tf(s[nt][0]), f2tf(s[nt][1]));
            *(uint2*)&Ss[(qrow + 8) * SS_STR + col] =
                make_uint2(f2tf(s[nt][2]), f2tf(s[nt][3]));
        }
        __syncwarp();

        // O += P @ V : k over 64 keys, 8 d-tiles
        #pragma unroll
        for (int k8 = 0; k8 < 8; k8++) {
            const int k0 = k8 * 8;
            uint32_t a[4];
            a[0] = Ss[qrow * SS_STR + k0 + (lane & 3)];
            a[1] = Ss[(qrow + 8) * SS_STR + k0 + (lane & 3)];
            a[2] = Ss[qrow * SS_STR + k0 + (lane & 3) + 4];
            a[3] = Ss[(qrow + 8) * SS_STR + k0 + (lane & 3) + 4];
            #pragma unroll
            for (int nt = 0; nt < 8; nt++) {
                uint32_t b0 = Vs[(k0 + (lane & 3)) * VS_STR + nt * 8 + (lane >> 2)];
                uint32_t b1 = Vs[(k0 + (lane & 3) + 4) * VS_STR + nt * 8 + (lane >> 2)];
                mma8(o[nt], a, b0, b1);
            }
        }
    }

    // epilogue
    float inv0 = 1.0f / l0, inv1 = 1.0f / l1;
    float* Op = g_O + ((size_t)bh * SEQ + q0) * DH;
    #pragma unroll
    for (int nt = 0; nt < 8; nt++) {
        int col = nt * 8 + (lane & 3) * 2;
        *(float2*)&Op[(size_t)qrow * DH + col] =
            make_float2(o[nt][0] * inv0, o[nt][1] * inv0);
        *(float2*)&Op[(size_t)(qrow + 8) * DH + col] =
            make_float2(o[nt][2] * inv1, o[nt][3] * inv1);
    }
}

// ---------------------------------------------------------------------------
extern "C" void kernel_launch(void* const* d_in, const int* in_sizes, int n_in,
                              void* d_out, int out_size)
{
    const float* x  = (const float*)d_in[0];
    const float* Wq = (const float*)d_in[1];
    const float* bq = (const float*)d_in[2];
    const float* Wk = (const float*)d_in[3];
    const float* bk = (const float*)d_in[4];
    const float* Wv = (const float*)d_in[5];
    const float* bv = (const float*)d_in[6];
    const float* Wo = (const float*)d_in[7];
    const float* bo = (const float*)d_in[8];
    (void)in_sizes; (void)n_in; (void)out_size;

    cudaFuncSetAttribute(tc_gemm_kernel,
                         cudaFuncAttributeMaxDynamicSharedMemorySize, GEMM_SMEM);
    cudaFuncSetAttribute(flash_kernel,
                         cudaFuncAttributeMaxDynamicSharedMemorySize, FLASH_SMEM);

    dim3 gg(D_MODEL / 128, MROWS / 128);  // (8, 32)

    const float scale = 0.125f;  // 1/sqrt(DH) folded into Q projection
    tc_gemm_kernel<<<gg, 256, GEMM_SMEM>>>(x, Wq, bq, nullptr, 0, scale);
    tc_gemm_kernel<<<gg, 256, GEMM_SMEM>>>(x, Wk, bk, nullptr, 1, 1.0f);
    tc_gemm_kernel<<<gg, 256, GEMM_SMEM>>>(x, Wv, bv, nullptr, 2, 1.0f);

    flash_kernel<<<dim3(SEQ / 128, BHN), 256, FLASH_SMEM>>>();

    tc_gemm_kernel<<<gg, 256, GEMM_SMEM>>>(x, Wo, bo, (float*)d_out, 3, 1.0f);
}